// round 8
// baseline (speedup 1.0000x reference)
#include <cuda_runtime.h>
#include <cuda_bf16.h>
#include <cstdint>

#define T_STEPS 2048
#define BATCH   64
#define HID     256
#define MROWS   (T_STEPS * BATCH)   // 131072
#define NSTREAM 10
#define NCHUNK  1024                // 128-row chunks
#define NTILE   (NCHUNK * 2)

// GEMM smem layout (bytes) — unchanged from R7 (validated)
#define SM_BIAS  0
#define SM_WHI   1024
#define WROWB    264
#define WBYTES   (128 * WROWB * 2)
#define SM_WLO   (SM_WHI + WBYTES)
#define SM_AHI   (SM_WLO + WBYTES)
#define AROWB    72
#define ABYTES   (128 * AROWB * 2)
#define SM_ALO   (SM_AHI + ABYTES)
#define GEMM_SMEM (SM_ALO + ABYTES)  // 173056

__device__ float g_buf0[(size_t)MROWS * HID];   // xp0 fp32
__device__ float g_buf2[(size_t)MROWS * HID];   // xp1 fp32
__device__ __nv_bfloat16 g_xhi[(size_t)MROWS * HID];
__device__ __nv_bfloat16 g_xlo[(size_t)MROWS * HID];
__device__ __nv_bfloat16 g_h1hi[(size_t)MROWS * HID];
__device__ __nv_bfloat16 g_h1lo[(size_t)MROWS * HID];
__device__ __nv_bfloat16 g_Whi[2][HID * HID];
__device__ __nv_bfloat16 g_Wlo[2][HID * HID];
__device__ int g_prog1[2][BATCH];               // per-rank layer-1 progress
__device__ int g_midflag[NTILE];

// ---------------------------------------------------------------------------
union F4U { float4 v; unsigned long long u[2]; };
__device__ __forceinline__ unsigned long long ffma2(
    unsigned long long a, unsigned long long b, unsigned long long c)
{
    unsigned long long d;
    asm("fma.rn.f32x2 %0, %1, %2, %3;" : "=l"(d) : "l"(a), "l"(b), "l"(c));
    return d;
}
__device__ __forceinline__ float2 up2(unsigned long long v)
{
    float2 r;
    asm("mov.b64 {%0, %1}, %2;" : "=f"(r.x), "=f"(r.y) : "l"(v));
    return r;
}
__device__ __forceinline__ int ld_acq(const int* p)
{
    int v;
    asm volatile("ld.acquire.gpu.global.b32 %0, [%1];" : "=r"(v) : "l"(p) : "memory");
    return v;
}
__device__ __forceinline__ void st_rel(int* p, int v)
{
    asm volatile("st.release.gpu.global.b32 [%0], %1;" :: "l"(p), "r"(v) : "memory");
}
__device__ __forceinline__ unsigned smem_u32(const void* p)
{
    unsigned a;
    asm("{ .reg .u64 t; cvta.to.shared.u64 t, %1; cvt.u32.u64 %0, t; }"
        : "=r"(a) : "l"(p));
    return a;
}
__device__ __forceinline__ unsigned mapa_u32(unsigned la, unsigned rank)
{
    unsigned ra;
    asm("mapa.shared::cluster.u32 %0, %1, %2;" : "=r"(ra) : "r"(la), "r"(rank));
    return ra;
}
__device__ __forceinline__ void st_cluster_f32(unsigned ra, float v)
{
    asm volatile("st.shared::cluster.f32 [%0], %1;" :: "r"(ra), "f"(v) : "memory");
}
__device__ __forceinline__ void mbar_arrive_remote_rel(unsigned ra)
{
    asm volatile("mbarrier.arrive.release.cluster.shared::cluster.b64 _, [%0];"
                 :: "r"(ra) : "memory");
}
__device__ __forceinline__ void mbar_wait_parity_acq_cluster(unsigned la, unsigned ph)
{
    asm volatile("{\n\t.reg .pred P1;\n\tWL_%=:\n\t"
        "mbarrier.try_wait.parity.acquire.cluster.shared::cta.b64 P1, [%0], %1;\n\t"
        "@P1 bra.uni WD_%=;\n\tbra.uni WL_%=;\n\tWD_%=:\n\t}"
        :: "r"(la), "r"(ph) : "memory");
}
#define MBAR_INIT(la, n) \
    asm volatile("mbarrier.init.shared.b64 [%0], %1;" :: "r"((unsigned)(la)), "r"((unsigned)(n)) : "memory")
#define CLUSTER_SYNC() do { \
    asm volatile("barrier.cluster.arrive.aligned;" ::: "memory"); \
    asm volatile("barrier.cluster.wait.aligned;" ::: "memory"); \
} while (0)

#define MMA_BF16(d, a, b) \
    asm volatile("mma.sync.aligned.m16n8k16.row.col.f32.bf16.bf16.f32 " \
        "{%0,%1,%2,%3},{%4,%5,%6,%7},{%8,%9},{%0,%1,%2,%3};" \
        : "+f"((d)[0]), "+f"((d)[1]), "+f"((d)[2]), "+f"((d)[3]) \
        : "r"((a)[0]), "r"((a)[1]), "r"((a)[2]), "r"((a)[3]), \
          "r"((b)[0]), "r"((b)[1]))

// ---------------------------------------------------------------------------
// Prep: zero flags, convert W_ih0/W_ih1 and x to bf16 hi/lo.
// ---------------------------------------------------------------------------
__global__ void prep_kernel(const float* __restrict__ x,
                            const float* __restrict__ Wih0,
                            const float* __restrict__ Wih1)
{
    int idx = blockIdx.x * blockDim.x + threadIdx.x;
    int nthr = gridDim.x * blockDim.x;
    if (blockIdx.x == 0) {
        int t = threadIdx.x;
        if (t < BATCH) { g_prog1[0][t] = 0; g_prog1[1][t] = 0; }
        for (int i = t; i < NTILE; i += blockDim.x) g_midflag[i] = 0;
    }
    for (int i = idx; i < 2 * HID * HID; i += nthr) {
        int m = i >> 16, e = i & 0xFFFF;
        float w = (m == 0 ? Wih0 : Wih1)[e];
        __nv_bfloat16 hi = __float2bfloat16(w);
        g_Whi[m][e] = hi;
        g_Wlo[m][e] = __float2bfloat16(w - __bfloat162float(hi));
    }
    for (size_t i = idx; i < (size_t)MROWS * HID; i += nthr) {
        float v = x[i];
        __nv_bfloat16 hi = __float2bfloat16(v);
        g_xhi[i] = hi;
        g_xlo[i] = __float2bfloat16(v - __bfloat162float(hi));
    }
}

// ---------------------------------------------------------------------------
// HMMA GEMM machinery (validated in R7)
// ---------------------------------------------------------------------------
__device__ __forceinline__ void mma_setup_w(
    char* sm, const __nv_bfloat16* Whig, const __nv_bfloat16* Wlog, int bn,
    const float* b1, const float* b2)
{
    const int tid = threadIdx.x;
    const int row = tid >> 1;
    const int seg = tid & 1;
    const uint4* ghi = reinterpret_cast<const uint4*>(
        Whig + (size_t)(bn + row) * 256 + seg * 128);
    const uint4* glo = reinterpret_cast<const uint4*>(
        Wlog + (size_t)(bn + row) * 256 + seg * 128);
    uint4* shi = reinterpret_cast<uint4*>(sm + SM_WHI + row * (WROWB*2) + seg * 256);
    uint4* slo = reinterpret_cast<uint4*>(sm + SM_WLO + row * (WROWB*2) + seg * 256);
    #pragma unroll
    for (int q = 0; q < 16; q++) { shi[q] = ghi[q]; slo[q] = glo[q]; }
    if (tid < 128) {
        int n = bn + tid;
        reinterpret_cast<float*>(sm + SM_BIAS)[tid] = b1[n] + b2[n];
    }
    __syncthreads();
}

__device__ __forceinline__ void mma_tile(
    const __nv_bfloat16* __restrict__ Ahig,
    const __nv_bfloat16* __restrict__ Alog,
    float* __restrict__ Crows, int bn, char* sm)
{
    const int tid  = threadIdx.x;
    const int lane = tid & 31;
    const int wid  = tid >> 5;
    const int g    = lane >> 2;
    const int tig  = lane & 3;
    const int m_base = (wid >> 1) * 32;
    const int n_base = (wid & 1) * 64;

    const uint32_t* Wwhi = reinterpret_cast<const uint32_t*>(sm + SM_WHI);
    const uint32_t* Wwlo = reinterpret_cast<const uint32_t*>(sm + SM_WLO);
    const uint32_t* Awhi = reinterpret_cast<const uint32_t*>(sm + SM_AHI);
    const uint32_t* Awlo = reinterpret_cast<const uint32_t*>(sm + SM_ALO);

    float acc[2][8][4];
    #pragma unroll
    for (int mf = 0; mf < 2; mf++)
        #pragma unroll
        for (int nf = 0; nf < 8; nf++)
            #pragma unroll
            for (int q = 0; q < 4; q++) acc[mf][nf][q] = 0.f;

    const int arow = tid >> 1;
    const int aseg = tid & 1;

    for (int kc = 0; kc < 4; kc++) {
        __syncthreads();
        {
            const uint4* ghi = reinterpret_cast<const uint4*>(
                Ahig + (size_t)arow * 256 + kc * 64 + aseg * 32);
            const uint4* glo = reinterpret_cast<const uint4*>(
                Alog + (size_t)arow * 256 + kc * 64 + aseg * 32);
            uint4* shi = reinterpret_cast<uint4*>(sm + SM_AHI + arow * (AROWB*2) + aseg * 64);
            uint4* slo = reinterpret_cast<uint4*>(sm + SM_ALO + arow * (AROWB*2) + aseg * 64);
            #pragma unroll
            for (int q = 0; q < 4; q++) { shi[q] = ghi[q]; slo[q] = glo[q]; }
        }
        __syncthreads();

        #pragma unroll
        for (int ks = 0; ks < 4; ks++) {
            const int kwl = ks * 8;
            const int kwg = kc * 32 + ks * 8;
            uint32_t ahi[2][4], alo[2][4], bhi[8][2], blo[8][2];
            #pragma unroll
            for (int mf = 0; mf < 2; mf++) {
                int r0 = (m_base + mf * 16 + g) * 36 + kwl + tig;
                int r1 = r0 + 8 * 36;
                ahi[mf][0] = Awhi[r0];     ahi[mf][1] = Awhi[r1];
                ahi[mf][2] = Awhi[r0 + 4]; ahi[mf][3] = Awhi[r1 + 4];
                alo[mf][0] = Awlo[r0];     alo[mf][1] = Awlo[r1];
                alo[mf][2] = Awlo[r0 + 4]; alo[mf][3] = Awlo[r1 + 4];
            }
            #pragma unroll
            for (int nf = 0; nf < 8; nf++) {
                int rb = (n_base + nf * 8 + g) * 132 + kwg + tig;
                bhi[nf][0] = Wwhi[rb]; bhi[nf][1] = Wwhi[rb + 4];
                blo[nf][0] = Wwlo[rb]; blo[nf][1] = Wwlo[rb + 4];
            }
            #pragma unroll
            for (int mf = 0; mf < 2; mf++)
                #pragma unroll
                for (int nf = 0; nf < 8; nf++) {
                    MMA_BF16(acc[mf][nf], ahi[mf], bhi[nf]);
                    MMA_BF16(acc[mf][nf], ahi[mf], blo[nf]);
                    MMA_BF16(acc[mf][nf], alo[mf], bhi[nf]);
                }
        }
    }

    const float* bias = reinterpret_cast<const float*>(sm + SM_BIAS);
    #pragma unroll
    for (int mf = 0; mf < 2; mf++) {
        int row0 = m_base + mf * 16 + g;
        #pragma unroll
        for (int nf = 0; nf < 8; nf++) {
            int col = n_base + nf * 8 + tig * 2;
            float2 o0 = { acc[mf][nf][0] + bias[col],
                          acc[mf][nf][1] + bias[col + 1] };
            float2 o1 = { acc[mf][nf][2] + bias[col],
                          acc[mf][nf][3] + bias[col + 1] };
            *reinterpret_cast<float2*>(&Crows[(size_t)row0 * 256 + bn + col]) = o0;
            *reinterpret_cast<float2*>(&Crows[(size_t)(row0 + 8) * 256 + bn + col]) = o1;
        }
    }
}

// ---------------------------------------------------------------------------
// Phase A: xp0 = x @ W_ih0^T + bias
// ---------------------------------------------------------------------------
__global__ __launch_bounds__(256, 1) void phase_a_kernel(
    const float* __restrict__ b_ih0, const float* __restrict__ b_hh0)
{
    extern __shared__ char sm[];
    const int half = blockIdx.x & 1;
    const int stream = blockIdx.x >> 1;
    const int bn = half * 128;
    mma_setup_w(sm, g_Whi[0], g_Wlo[0], bn, b_ih0, b_hh0);
    for (int c = stream; c < NCHUNK; c += 74)
        mma_tile(g_xhi + (size_t)c * 128 * 256, g_xlo + (size_t)c * 128 * 256,
                 g_buf0 + (size_t)c * 128 * 256, bn, sm);
}

// ---------------------------------------------------------------------------
// K-split cluster scan role. 2 CTAs per batch; CTA rank r holds W rows for
// k in [128r, 128r+128) entirely in registers, computes partials for ALL 256
// outputs, exchanges the peer-owned 128 partials via DSMEM each step.
// CTA r finalizes outputs [128r, 128r+128) == exactly the h its k-half needs.
// ---------------------------------------------------------------------------
__device__ __forceinline__ void scan_k2_role(
    const float* __restrict__ xp, const float* __restrict__ Whh,
    int b, int rank,
    __nv_bfloat16* outhi, __nv_bfloat16* outlo, int* prog_out,  // layer1
    float* outf)                                                 // layer2
{
    __shared__ __align__(16) float hbuf[2][128];
    __shared__ __align__(16) float recvb[2][128];
    __shared__ __align__(8) unsigned long long mbar[2];

    const int l = threadIdx.x;
    const int lj = l & 127;
    const bool owner = (l >> 7) == rank;

    // W row l, k-half `rank` -> 64 packed f32x2 in registers
    unsigned long long w2[64];
    const float4* wrow = reinterpret_cast<const float4*>(
        Whh + (size_t)l * HID + rank * 128);
    #pragma unroll
    for (int i = 0; i < 32; i++) {
        F4U v; v.v = wrow[i];
        w2[2*i] = v.u[0]; w2[2*i+1] = v.u[1];
    }

    if (l < 128) hbuf[0][l] = 0.f;
    if (l == 0) {
        MBAR_INIT(smem_u32(&mbar[0]), 128);
        MBAR_INIT(smem_u32(&mbar[1]), 128);
    }
    __syncthreads();
    CLUSTER_SYNC();   // peer mbar init visible before any remote arrive

    const unsigned peer = (unsigned)(rank ^ 1);
    unsigned ra_recv[2], ra_mb[2], la_mb[2];
    ra_recv[0] = mapa_u32(smem_u32(&recvb[0][lj]), peer);
    ra_recv[1] = mapa_u32(smem_u32(&recvb[1][lj]), peer);
    ra_mb[0]   = mapa_u32(smem_u32(&mbar[0]), peer);
    ra_mb[1]   = mapa_u32(smem_u32(&mbar[1]), peer);
    la_mb[0]   = smem_u32(&mbar[0]);
    la_mb[1]   = smem_u32(&mbar[1]);

    const size_t stride = (size_t)BATCH * HID;
    const size_t base   = (size_t)b * HID + l;   // output index j == l

    int cur = 0;
    for (int t = 0; t < T_STEPS; t++) {
        const int par = t & 1;
        const unsigned ph = (unsigned)((t >> 1) & 1);

        float xv = 0.f;
        if (owner) xv = xp[(size_t)t * stride + base];

        const float4* h4 = reinterpret_cast<const float4*>(hbuf[cur]);
        unsigned long long a0 = 0ull, a1 = 0ull, a2 = 0ull, a3 = 0ull;
        #pragma unroll
        for (int i = 0; i < 32; i += 2) {
            F4U hv0; hv0.v = h4[i];
            a0 = ffma2(w2[2*i],   hv0.u[0], a0);
            a1 = ffma2(w2[2*i+1], hv0.u[1], a1);
            F4U hv1; hv1.v = h4[i+1];
            a2 = ffma2(w2[2*i+2], hv1.u[0], a2);
            a3 = ffma2(w2[2*i+3], hv1.u[1], a3);
        }
        float2 s0 = up2(a0), s1 = up2(a1), s2 = up2(a2), s3 = up2(a3);
        float p = ((s0.x + s0.y) + (s1.x + s1.y))
                + ((s2.x + s2.y) + (s3.x + s3.y));

        if (!owner) {
            // send partial for peer-owned output to peer's recv, signal
            st_cluster_f32(ra_recv[par], p);
            mbar_arrive_remote_rel(ra_mb[par]);
        } else {
            mbar_wait_parity_acq_cluster(la_mb[par], ph);
            float h = tanhf(xv + p + recvb[par][lj]);
            hbuf[cur ^ 1][lj] = h;
            if (outf) {
                outf[(size_t)t * stride + base] = h;
            } else {
                __nv_bfloat16 hv = __float2bfloat16(h);
                outhi[(size_t)t * stride + base] = hv;
                outlo[(size_t)t * stride + base] =
                    __float2bfloat16(h - __bfloat162float(hv));
            }
        }
        __syncthreads();
        if (prog_out && l == (rank << 7)) st_rel(prog_out, t + 1);
        cur ^= 1;
    }
    CLUSTER_SYNC();
}

// ---------------------------------------------------------------------------
// K3: 148 CTAs (74 clusters of 2).
//   bid 0..127  : layer-1 K-split scan (cluster bid>>1 = batch, rank bid&1)
//   bid 128..147: HMMA xp1 workers (poll both rank progs)
// ---------------------------------------------------------------------------
__global__ __launch_bounds__(256, 1) void scan1_mid_kernel(
    const float* __restrict__ W_hh0,
    const float* __restrict__ b_ih1,
    const float* __restrict__ b_hh1)
{
    extern __shared__ char smraw[];
    const int bid = blockIdx.x;

    if (bid < 128) {
        const int b = bid >> 1, rank = bid & 1;
        scan_k2_role(g_buf0, W_hh0, b, rank,
                     g_h1hi, g_h1lo, &g_prog1[rank][b], nullptr);
    } else {
        const int w = bid - 128;
        const int half = w & 1;
        const int stream = w >> 1;
        const int bn = half * 128;
        const int tid = threadIdx.x;

        mma_setup_w(smraw, g_Whi[1], g_Wlo[1], bn, b_ih1, b_hh1);
        for (int c = stream; c < NCHUNK; c += NSTREAM) {
            if (tid < 128) {
                int rr = tid >> 6, bb = tid & 63;
                while (ld_acq(&g_prog1[rr][bb]) < 2 * c + 2) __nanosleep(200);
            }
            __syncthreads();
            mma_tile(g_h1hi + (size_t)c * 128 * 256,
                     g_h1lo + (size_t)c * 128 * 256,
                     g_buf2 + (size_t)c * 128 * 256, bn, smraw);
            __syncthreads();
            if (tid == 0) st_rel(&g_midflag[c * 2 + half], 1);
        }
    }
}

// ---------------------------------------------------------------------------
// K4: layer-2 K-split scan, 128 CTAs (64 clusters). xp1 fully materialized.
// ---------------------------------------------------------------------------
__global__ __launch_bounds__(256, 1) void scan2_kernel(
    const float* __restrict__ W_hh1, float* __restrict__ out)
{
    const int b = blockIdx.x >> 1, rank = blockIdx.x & 1;
    scan_k2_role(g_buf2, W_hh1, b, rank, nullptr, nullptr, nullptr, out);
}

// ---------------------------------------------------------------------------
extern "C" void kernel_launch(void* const* d_in, const int* in_sizes, int n_in,
                              void* d_out, int out_size)
{
    const float* x     = (const float*)d_in[0];
    const float* W_ih0 = (const float*)d_in[1];
    const float* W_hh0 = (const float*)d_in[2];
    const float* b_ih0 = (const float*)d_in[3];
    const float* b_hh0 = (const float*)d_in[4];
    const float* W_ih1 = (const float*)d_in[5];
    const float* W_hh1 = (const float*)d_in[6];
    const float* b_ih1 = (const float*)d_in[7];
    const float* b_hh1 = (const float*)d_in[8];
    float* out = (float*)d_out;

    cudaFuncSetAttribute(phase_a_kernel,
                         cudaFuncAttributeMaxDynamicSharedMemorySize, GEMM_SMEM);
    cudaFuncSetAttribute(scan1_mid_kernel,
                         cudaFuncAttributeMaxDynamicSharedMemorySize, GEMM_SMEM);

    prep_kernel<<<1024, 256>>>(x, W_ih0, W_ih1);
    phase_a_kernel<<<148, 256, GEMM_SMEM>>>(b_ih0, b_hh0);

    {   // K3: clustered scan1 + workers
        cudaLaunchConfig_t cfg = {};
        cfg.gridDim = dim3(148, 1, 1);
        cfg.blockDim = dim3(256, 1, 1);
        cfg.dynamicSmemBytes = GEMM_SMEM;
        cudaLaunchAttribute at[1];
        at[0].id = cudaLaunchAttributeClusterDimension;
        at[0].val.clusterDim = {2, 1, 1};
        cfg.attrs = at;
        cfg.numAttrs = 1;
        cudaLaunchKernelEx(&cfg, scan1_mid_kernel, W_hh0, b_ih1, b_hh1);
    }
    {   // K4: clustered scan2
        cudaLaunchConfig_t cfg = {};
        cfg.gridDim = dim3(128, 1, 1);
        cfg.blockDim = dim3(256, 1, 1);
        cfg.dynamicSmemBytes = 0;
        cudaLaunchAttribute at[1];
        at[0].id = cudaLaunchAttributeClusterDimension;
        at[0].val.clusterDim = {2, 1, 1};
        cfg.attrs = at;
        cfg.numAttrs = 1;
        cudaLaunchKernelEx(&cfg, scan2_kernel, W_hh1, out);
    }
}

// round 10
// speedup vs baseline: 1.3809x; 1.3809x over previous
#include <cuda_runtime.h>
#include <cuda_bf16.h>
#include <cstdint>

#define T_STEPS 2048
#define BATCH   64
#define HID     256
#define MROWS   (T_STEPS * BATCH)   // 131072
#define NCHUNK  1024                // 128-row (=2-step) chunks
#define NTILE   (NCHUNK * 2)
#define NPA     42                  // phase-A streams (84 CTAs / 2 halves)
#define NWSTR   10                  // worker streams (20 CTAs / 2 halves)

// GEMM smem layout (bytes) — validated in R7
#define SM_BIAS  0
#define SM_WHI   1024
#define WROWB    264
#define WBYTES   (128 * WROWB * 2)
#define SM_WLO   (SM_WHI + WBYTES)
#define SM_AHI   (SM_WLO + WBYTES)
#define AROWB    72
#define ABYTES   (128 * AROWB * 2)
#define SM_ALO   (SM_AHI + ABYTES)
#define GEMM_SMEM (SM_ALO + ABYTES)  // 173056

// Scan smem: Wt stride 29 float4 (112 floats W + pad): 256*29*16 = 118784 < GEMM_SMEM

__device__ float g_buf0[(size_t)MROWS * HID];   // xp0 fp32
__device__ float g_buf2[(size_t)MROWS * HID];   // xp1 fp32
__device__ __nv_bfloat16 g_h1hi[(size_t)MROWS * HID];
__device__ __nv_bfloat16 g_h1lo[(size_t)MROWS * HID];
__device__ __nv_bfloat16 g_Whi[2][HID * HID];
__device__ __nv_bfloat16 g_Wlo[2][HID * HID];
__device__ int g_prog1[BATCH];
__device__ int g_xp0flag[NTILE];
__device__ int g_midflag[NTILE];

// ---------------------------------------------------------------------------
union F4U { float4 v; unsigned long long u[2]; };
__device__ __forceinline__ unsigned long long ffma2(
    unsigned long long a, unsigned long long b, unsigned long long c)
{
    unsigned long long d;
    asm("fma.rn.f32x2 %0, %1, %2, %3;" : "=l"(d) : "l"(a), "l"(b), "l"(c));
    return d;
}
__device__ __forceinline__ float2 up2(unsigned long long v)
{
    float2 r;
    asm("mov.b64 {%0, %1}, %2;" : "=f"(r.x), "=f"(r.y) : "l"(v));
    return r;
}
__device__ __forceinline__ int ld_acq(const int* p)
{
    int v;
    asm volatile("ld.acquire.gpu.global.b32 %0, [%1];" : "=r"(v) : "l"(p) : "memory");
    return v;
}
__device__ __forceinline__ void st_rel(int* p, int v)
{
    asm volatile("st.release.gpu.global.b32 [%0], %1;" :: "l"(p), "r"(v) : "memory");
}

#define MMA_BF16(d, a, b) \
    asm volatile("mma.sync.aligned.m16n8k16.row.col.f32.bf16.bf16.f32 " \
        "{%0,%1,%2,%3},{%4,%5,%6,%7},{%8,%9},{%0,%1,%2,%3};" \
        : "+f"((d)[0]), "+f"((d)[1]), "+f"((d)[2]), "+f"((d)[3]) \
        : "r"((a)[0]), "r"((a)[1]), "r"((a)[2]), "r"((a)[3]), \
          "r"((b)[0]), "r"((b)[1]))

// ---------------------------------------------------------------------------
// Prep: zero flags, convert W_ih0/W_ih1 to bf16 hi/lo. (~10us)
// ---------------------------------------------------------------------------
__global__ void prep_kernel(const float* __restrict__ Wih0,
                            const float* __restrict__ Wih1)
{
    int idx = blockIdx.x * blockDim.x + threadIdx.x;
    int nthr = gridDim.x * blockDim.x;
    for (int i = idx; i < NTILE; i += nthr) { g_xp0flag[i] = 0; g_midflag[i] = 0; }
    if (idx < BATCH) g_prog1[idx] = 0;
    for (int i = idx; i < 2 * HID * HID; i += nthr) {
        int m = i >> 16, e = i & 0xFFFF;
        float w = (m == 0 ? Wih0 : Wih1)[e];
        __nv_bfloat16 hi = __float2bfloat16(w);
        g_Whi[m][e] = hi;
        g_Wlo[m][e] = __float2bfloat16(w - __bfloat162float(hi));
    }
}

// ---------------------------------------------------------------------------
// Stage W half + bias into smem (validated R7)
// ---------------------------------------------------------------------------
__device__ __forceinline__ void mma_setup_w(
    char* sm, const __nv_bfloat16* Whig, const __nv_bfloat16* Wlog, int bn,
    const float* b1, const float* b2)
{
    const int tid = threadIdx.x;
    const int row = tid >> 1;
    const int seg = tid & 1;
    const uint4* ghi = reinterpret_cast<const uint4*>(
        Whig + (size_t)(bn + row) * 256 + seg * 128);
    const uint4* glo = reinterpret_cast<const uint4*>(
        Wlog + (size_t)(bn + row) * 256 + seg * 128);
    uint4* shi = reinterpret_cast<uint4*>(sm + SM_WHI + row * (WROWB*2) + seg * 256);
    uint4* slo = reinterpret_cast<uint4*>(sm + SM_WLO + row * (WROWB*2) + seg * 256);
    #pragma unroll
    for (int q = 0; q < 16; q++) { shi[q] = ghi[q]; slo[q] = glo[q]; }
    if (tid < 128) {
        int n = bn + tid;
        reinterpret_cast<float*>(sm + SM_BIAS)[tid] = b1[n] + b2[n];
    }
    __syncthreads();
}

// ---------------------------------------------------------------------------
// Shared MMA compute core: fragments + 48 HMMA per k-chunk + epilogue.
// A staged in smem by the caller-provided loader each k-chunk.
// Variadic so brace-level commas in STAGE_A are preserved.
// ---------------------------------------------------------------------------
#define MMA_CORE_BODY(...)                                                      \
    const int tid  = threadIdx.x;                                               \
    const int lane = tid & 31;                                                  \
    const int wid  = tid >> 5;                                                  \
    const int g    = lane >> 2;                                                 \
    const int tig  = lane & 3;                                                  \
    const int m_base = (wid >> 1) * 32;                                         \
    const int n_base = (wid & 1) * 64;                                          \
    const uint32_t* Wwhi = reinterpret_cast<const uint32_t*>(sm + SM_WHI);      \
    const uint32_t* Wwlo = reinterpret_cast<const uint32_t*>(sm + SM_WLO);      \
    const uint32_t* Awhi = reinterpret_cast<const uint32_t*>(sm + SM_AHI);      \
    const uint32_t* Awlo = reinterpret_cast<const uint32_t*>(sm + SM_ALO);      \
    float acc[2][8][4];                                                         \
    _Pragma("unroll")                                                           \
    for (int mf = 0; mf < 2; mf++)                                              \
        _Pragma("unroll")                                                       \
        for (int nf = 0; nf < 8; nf++)                                          \
            _Pragma("unroll")                                                   \
            for (int q = 0; q < 4; q++) acc[mf][nf][q] = 0.f;                   \
    const int arow = tid >> 1;                                                  \
    const int aseg = tid & 1;                                                   \
    for (int kc = 0; kc < 4; kc++) {                                            \
        __syncthreads();                                                        \
        __VA_ARGS__;                                                            \
        __syncthreads();                                                        \
        _Pragma("unroll")                                                       \
        for (int ks = 0; ks < 4; ks++) {                                        \
            const int kwl = ks * 8;                                             \
            const int kwg = kc * 32 + ks * 8;                                   \
            uint32_t ahi[2][4];                                                 \
            uint32_t alo[2][4];                                                 \
            uint32_t bhi[8][2];                                                 \
            uint32_t blo[8][2];                                                 \
            _Pragma("unroll")                                                   \
            for (int mf = 0; mf < 2; mf++) {                                    \
                int r0 = (m_base + mf * 16 + g) * 36 + kwl + tig;               \
                int r1 = r0 + 8 * 36;                                           \
                ahi[mf][0] = Awhi[r0];     ahi[mf][1] = Awhi[r1];               \
                ahi[mf][2] = Awhi[r0 + 4]; ahi[mf][3] = Awhi[r1 + 4];           \
                alo[mf][0] = Awlo[r0];     alo[mf][1] = Awlo[r1];               \
                alo[mf][2] = Awlo[r0 + 4]; alo[mf][3] = Awlo[r1 + 4];           \
            }                                                                   \
            _Pragma("unroll")                                                   \
            for (int nf = 0; nf < 8; nf++) {                                    \
                int rb = (n_base + nf * 8 + g) * 132 + kwg + tig;               \
                bhi[nf][0] = Wwhi[rb]; bhi[nf][1] = Wwhi[rb + 4];               \
                blo[nf][0] = Wwlo[rb]; blo[nf][1] = Wwlo[rb + 4];               \
            }                                                                   \
            _Pragma("unroll")                                                   \
            for (int mf = 0; mf < 2; mf++)                                      \
                _Pragma("unroll")                                               \
                for (int nf = 0; nf < 8; nf++) {                                \
                    MMA_BF16(acc[mf][nf], ahi[mf], bhi[nf]);                    \
                    MMA_BF16(acc[mf][nf], ahi[mf], blo[nf]);                    \
                    MMA_BF16(acc[mf][nf], alo[mf], bhi[nf]);                    \
                }                                                               \
        }                                                                       \
    }                                                                           \
    const float* bias = reinterpret_cast<const float*>(sm + SM_BIAS);           \
    _Pragma("unroll")                                                           \
    for (int mf = 0; mf < 2; mf++) {                                            \
        int row0 = m_base + mf * 16 + g;                                        \
        _Pragma("unroll")                                                       \
        for (int nf = 0; nf < 8; nf++) {                                        \
            int col = n_base + nf * 8 + tig * 2;                                \
            float2 o0 = { acc[mf][nf][0] + bias[col],                           \
                          acc[mf][nf][1] + bias[col + 1] };                     \
            float2 o1 = { acc[mf][nf][2] + bias[col],                           \
                          acc[mf][nf][3] + bias[col + 1] };                     \
            *reinterpret_cast<float2*>(&Crows[(size_t)row0 * 256 + bn + col]) = o0;      \
            *reinterpret_cast<float2*>(&Crows[(size_t)(row0 + 8) * 256 + bn + col]) = o1;\
        }                                                                       \
    }

// A from precomputed bf16 hi/lo (worker path, validated R7)
__device__ __forceinline__ void mma_tile_bf16(
    const __nv_bfloat16* __restrict__ Ahig,
    const __nv_bfloat16* __restrict__ Alog,
    float* __restrict__ Crows, int bn, char* sm)
{
    MMA_CORE_BODY({
        const uint4* ghi = reinterpret_cast<const uint4*>(
            Ahig + (size_t)arow * 256 + kc * 64 + aseg * 32);
        const uint4* glo = reinterpret_cast<const uint4*>(
            Alog + (size_t)arow * 256 + kc * 64 + aseg * 32);
        uint4* shi = reinterpret_cast<uint4*>(sm + SM_AHI + arow * (AROWB*2) + aseg * 64);
        uint4* slo = reinterpret_cast<uint4*>(sm + SM_ALO + arow * (AROWB*2) + aseg * 64);
        _Pragma("unroll")
        for (int q = 0; q < 4; q++) { shi[q] = ghi[q]; slo[q] = glo[q]; }
    });
}

// A from fp32, converted to hi/lo during staging (phase-A path)
__device__ __forceinline__ void mma_tile_f32(
    const float* __restrict__ Arows,
    float* __restrict__ Crows, int bn, char* sm)
{
    MMA_CORE_BODY({
        const float4* gf = reinterpret_cast<const float4*>(
            Arows + (size_t)arow * 256 + kc * 64 + aseg * 32);
        uint32_t hw[16];
        uint32_t lw[16];
        _Pragma("unroll")
        for (int q = 0; q < 8; q++) {
            float4 f = gf[q];
            __nv_bfloat162 h0 = __floats2bfloat162_rn(f.x, f.y);
            __nv_bfloat162 h1 = __floats2bfloat162_rn(f.z, f.w);
            float lx = f.x - __bfloat162float(h0.x);
            float ly = f.y - __bfloat162float(h0.y);
            float lz = f.z - __bfloat162float(h1.x);
            float lw2 = f.w - __bfloat162float(h1.y);
            __nv_bfloat162 l0 = __floats2bfloat162_rn(lx, ly);
            __nv_bfloat162 l1 = __floats2bfloat162_rn(lz, lw2);
            hw[2*q]   = *reinterpret_cast<uint32_t*>(&h0);
            hw[2*q+1] = *reinterpret_cast<uint32_t*>(&h1);
            lw[2*q]   = *reinterpret_cast<uint32_t*>(&l0);
            lw[2*q+1] = *reinterpret_cast<uint32_t*>(&l1);
        }
        uint4* shi = reinterpret_cast<uint4*>(sm + SM_AHI + arow * (AROWB*2) + aseg * 64);
        uint4* slo = reinterpret_cast<uint4*>(sm + SM_ALO + arow * (AROWB*2) + aseg * 64);
        _Pragma("unroll")
        for (int q = 0; q < 4; q++) {
            shi[q] = make_uint4(hw[4*q], hw[4*q+1], hw[4*q+2], hw[4*q+3]);
            slo[q] = make_uint4(lw[4*q], lw[4*q+1], lw[4*q+2], lw[4*q+3]);
        }
    });
}

// ---------------------------------------------------------------------------
// Scan role: thread j owns output j. W row j: 144 floats in regs (72 u64),
// 112 in smem (28 float4, stride 29). Double-buffered h, 1 barrier/step.
// Polls input-ready flags every 8 steps with 4-chunk lookahead.
// ---------------------------------------------------------------------------
__device__ __forceinline__ void scan_role(
    const float* __restrict__ xp, const float* __restrict__ Whh,
    int b, float4* Wt,
    __nv_bfloat16* outhi, __nv_bfloat16* outlo, int* prog_out,   // layer1
    float* outf,                                                  // layer2
    const int* poll_flags)
{
    __shared__ __align__(16) float hbuf[2][HID];
    const int j = threadIdx.x;

    unsigned long long w2[72];
    const float4* wrow = reinterpret_cast<const float4*>(Whh + (size_t)j * HID);
    #pragma unroll
    for (int i = 0; i < 36; i++) {
        F4U v; v.v = wrow[i];
        w2[2*i] = v.u[0]; w2[2*i+1] = v.u[1];
    }
    #pragma unroll
    for (int i = 0; i < 28; i++)
        Wt[j * 29 + i] = wrow[36 + i];

    hbuf[0][j] = 0.f;
    __syncthreads();

    const float4* wsrow  = &Wt[j * 29];
    const size_t  stride = (size_t)BATCH * HID;
    const size_t  base   = (size_t)b * HID + j;

    int cur = 0;
    for (int t = 0; t < T_STEPS; t++) {
        if (poll_flags && (t & 7) == 0) {
            int c0 = t >> 1;
            if (j < 8) {
                const int* f = &poll_flags[(c0 + (j >> 1)) * 2 + (j & 1)];
                while (ld_acq(f) == 0) __nanosleep(100);
            }
            __syncthreads();
        }

        float xv = xp[(size_t)t * stride + base];

        const float4* h4 = reinterpret_cast<const float4*>(hbuf[cur]);
        unsigned long long a0 = 0ull, a1 = 0ull, a2 = 0ull, a3 = 0ull;

        #pragma unroll
        for (int i = 0; i < 36; i += 2) {      // k in [0,144): W in regs
            F4U hv0; hv0.v = h4[i];
            a0 = ffma2(w2[2*i],   hv0.u[0], a0);
            a1 = ffma2(w2[2*i+1], hv0.u[1], a1);
            F4U hv1; hv1.v = h4[i+1];
            a2 = ffma2(w2[2*i+2], hv1.u[0], a2);
            a3 = ffma2(w2[2*i+3], hv1.u[1], a3);
        }
        #pragma unroll
        for (int i = 0; i < 28; i += 2) {      // k in [144,256): W in smem
            F4U wv0; wv0.v = wsrow[i];
            F4U hv0; hv0.v = h4[36 + i];
            a0 = ffma2(wv0.u[0], hv0.u[0], a0);
            a1 = ffma2(wv0.u[1], hv0.u[1], a1);
            F4U wv1; wv1.v = wsrow[i+1];
            F4U hv1; hv1.v = h4[37 + i];
            a2 = ffma2(wv1.u[0], hv1.u[0], a2);
            a3 = ffma2(wv1.u[1], hv1.u[1], a3);
        }

        float2 s0 = up2(a0), s1 = up2(a1), s2 = up2(a2), s3 = up2(a3);
        float sum = ((s0.x + s0.y) + (s1.x + s1.y))
                  + ((s2.x + s2.y) + (s3.x + s3.y)) + xv;
        float h = tanhf(sum);

        hbuf[cur ^ 1][j] = h;
        if (outf) {
            outf[(size_t)t * stride + base] = h;
        } else {
            __nv_bfloat16 hv = __float2bfloat16(h);
            outhi[(size_t)t * stride + base] = hv;
            outlo[(size_t)t * stride + base] =
                __float2bfloat16(h - __bfloat162float(hv));
        }
        __syncthreads();
        if (prog_out && j == 0) st_rel(prog_out, t + 1);
        cur ^= 1;
    }
}

// ---------------------------------------------------------------------------
// Pipeline: 148 CTAs, everything after prep.
//   bid 0..63   : layer-1 scan (polls g_xp0flag) -> h1 bf16, publishes prog1
//   bid 64..147 : FIRST phase-A streams (xp0 = x@W_ih0^T+b, sets g_xp0flag)
//     then bid 64..127 : layer-2 scan (polls g_midflag) -> out
//          bid 128..147: HMMA xp1 workers (poll prog1, set g_midflag)
// ---------------------------------------------------------------------------
__global__ __launch_bounds__(256, 1) void pipeline_kernel(
    const float* __restrict__ x,
    const float* __restrict__ W_hh0,
    const float* __restrict__ b_ih0, const float* __restrict__ b_hh0,
    const float* __restrict__ b_ih1, const float* __restrict__ b_hh1,
    const float* __restrict__ W_hh1,
    float* __restrict__ out)
{
    extern __shared__ char sm[];
    const int bid = blockIdx.x;
    const int tid = threadIdx.x;

    if (bid < 64) {
        scan_role(g_buf0, W_hh0, bid, reinterpret_cast<float4*>(sm),
                  g_h1hi, g_h1lo, &g_prog1[bid], nullptr, g_xp0flag);
        return;
    }

    // ---- phase A: xp0 chunks in ascending order ----
    {
        const int s = bid - 64;          // 0..83
        const int half = s & 1;
        const int bn = half * 128;
        const int stream = s >> 1;       // 0..41
        mma_setup_w(sm, g_Whi[0], g_Wlo[0], bn, b_ih0, b_hh0);
        for (int c = stream; c < NCHUNK; c += NPA) {
            mma_tile_f32(x + (size_t)c * 128 * 256,
                         g_buf0 + (size_t)c * 128 * 256, bn, sm);
            __syncthreads();
            if (tid == 0) st_rel(&g_xp0flag[c * 2 + half], 1);
        }
        __syncthreads();
    }

    if (bid < 128) {
        // ---- layer-2 scan ----
        scan_role(g_buf2, W_hh1, bid - 64, reinterpret_cast<float4*>(sm),
                  nullptr, nullptr, nullptr, out, g_midflag);
    } else {
        // ---- xp1 workers ----
        const int w = bid - 128;         // 0..19
        const int half = w & 1;
        const int bn = half * 128;
        const int stream = w >> 1;       // 0..9
        mma_setup_w(sm, g_Whi[1], g_Wlo[1], bn, b_ih1, b_hh1);
        for (int c = stream; c < NCHUNK; c += NWSTR) {
            if (tid < BATCH)
                while (ld_acq(&g_prog1[tid]) < 2 * c + 2) __nanosleep(200);
            __syncthreads();
            mma_tile_bf16(g_h1hi + (size_t)c * 128 * 256,
                          g_h1lo + (size_t)c * 128 * 256,
                          g_buf2 + (size_t)c * 128 * 256, bn, sm);
            __syncthreads();
            if (tid == 0) st_rel(&g_midflag[c * 2 + half], 1);
        }
    }
}

// ---------------------------------------------------------------------------
extern "C" void kernel_launch(void* const* d_in, const int* in_sizes, int n_in,
                              void* d_out, int out_size)
{
    const float* x     = (const float*)d_in[0];
    const float* W_ih0 = (const float*)d_in[1];
    const float* W_hh0 = (const float*)d_in[2];
    const float* b_ih0 = (const float*)d_in[3];
    const float* b_hh0 = (const float*)d_in[4];
    const float* W_ih1 = (const float*)d_in[5];
    const float* W_hh1 = (const float*)d_in[6];
    const float* b_ih1 = (const float*)d_in[7];
    const float* b_hh1 = (const float*)d_in[8];
    float* out = (float*)d_out;

    cudaFuncSetAttribute(pipeline_kernel,
                         cudaFuncAttributeMaxDynamicSharedMemorySize, GEMM_SMEM);

    prep_kernel<<<64, 256>>>(W_ih0, W_ih1);
    pipeline_kernel<<<148, 256, GEMM_SMEM>>>(
        x, W_hh0, b_ih0, b_hh0, b_ih1, b_hh1, W_hh1, out);
}

// round 11
// speedup vs baseline: 1.4106x; 1.0215x over previous
#include <cuda_runtime.h>
#include <cuda_bf16.h>
#include <cstdint>

#define T_STEPS 2048
#define BATCH   64
#define HID     256
#define MROWS   (T_STEPS * BATCH)   // 131072
#define NCHUNK  1024                // 128-row (=2-step) chunks
#define NTILE   (NCHUNK * 2)
#define NPA     42                  // phase-A streams (84 CTAs / 2 halves)
#define NWSTR   10                  // worker streams (20 CTAs / 2 halves)

// GEMM smem layout (bytes) — validated in R7
#define SM_BIAS  0
#define SM_WHI   1024
#define WROWB    264
#define WBYTES   (128 * WROWB * 2)
#define SM_WLO   (SM_WHI + WBYTES)
#define SM_AHI   (SM_WLO + WBYTES)
#define AROWB    72
#define ABYTES   (128 * AROWB * 2)
#define SM_ALO   (SM_AHI + ABYTES)
#define GEMM_SMEM (SM_ALO + ABYTES)  // 173056

// Scan smem: Wt stride 33 float4 (128 floats W + pad): 256*33*16 = 135168 < GEMM_SMEM

__device__ float g_buf0[(size_t)MROWS * HID];   // xp0 fp32
__device__ float g_buf2[(size_t)MROWS * HID];   // xp1 fp32
__device__ __nv_bfloat16 g_h1hi[(size_t)MROWS * HID];
__device__ __nv_bfloat16 g_h1lo[(size_t)MROWS * HID];
__device__ __nv_bfloat16 g_Whi[2][HID * HID];
__device__ __nv_bfloat16 g_Wlo[2][HID * HID];
__device__ int g_prog1[BATCH];
__device__ int g_xp0flag[NTILE];
__device__ int g_midflag[NTILE];

// ---------------------------------------------------------------------------
union F4U { float4 v; unsigned long long u[2]; };
__device__ __forceinline__ unsigned long long ffma2(
    unsigned long long a, unsigned long long b, unsigned long long c)
{
    unsigned long long d;
    asm("fma.rn.f32x2 %0, %1, %2, %3;" : "=l"(d) : "l"(a), "l"(b), "l"(c));
    return d;
}
__device__ __forceinline__ float2 up2(unsigned long long v)
{
    float2 r;
    asm("mov.b64 {%0, %1}, %2;" : "=f"(r.x), "=f"(r.y) : "l"(v));
    return r;
}
__device__ __forceinline__ int ld_acq(const int* p)
{
    int v;
    asm volatile("ld.acquire.gpu.global.b32 %0, [%1];" : "=r"(v) : "l"(p) : "memory");
    return v;
}
__device__ __forceinline__ void st_rel(int* p, int v)
{
    asm volatile("st.release.gpu.global.b32 [%0], %1;" :: "l"(p), "r"(v) : "memory");
}

#define MMA_BF16(d, a, b) \
    asm volatile("mma.sync.aligned.m16n8k16.row.col.f32.bf16.bf16.f32 " \
        "{%0,%1,%2,%3},{%4,%5,%6,%7},{%8,%9},{%0,%1,%2,%3};" \
        : "+f"((d)[0]), "+f"((d)[1]), "+f"((d)[2]), "+f"((d)[3]) \
        : "r"((a)[0]), "r"((a)[1]), "r"((a)[2]), "r"((a)[3]), \
          "r"((b)[0]), "r"((b)[1]))

// ---------------------------------------------------------------------------
// Prep: zero flags, convert W_ih0/W_ih1 to bf16 hi/lo. (~10us)
// ---------------------------------------------------------------------------
__global__ void prep_kernel(const float* __restrict__ Wih0,
                            const float* __restrict__ Wih1)
{
    int idx = blockIdx.x * blockDim.x + threadIdx.x;
    int nthr = gridDim.x * blockDim.x;
    for (int i = idx; i < NTILE; i += nthr) { g_xp0flag[i] = 0; g_midflag[i] = 0; }
    if (idx < BATCH) g_prog1[idx] = 0;
    for (int i = idx; i < 2 * HID * HID; i += nthr) {
        int m = i >> 16, e = i & 0xFFFF;
        float w = (m == 0 ? Wih0 : Wih1)[e];
        __nv_bfloat16 hi = __float2bfloat16(w);
        g_Whi[m][e] = hi;
        g_Wlo[m][e] = __float2bfloat16(w - __bfloat162float(hi));
    }
}

// ---------------------------------------------------------------------------
// Stage W half + bias into smem (validated R7)
// ---------------------------------------------------------------------------
__device__ __forceinline__ void mma_setup_w(
    char* sm, const __nv_bfloat16* Whig, const __nv_bfloat16* Wlog, int bn,
    const float* b1, const float* b2)
{
    const int tid = threadIdx.x;
    const int row = tid >> 1;
    const int seg = tid & 1;
    const uint4* ghi = reinterpret_cast<const uint4*>(
        Whig + (size_t)(bn + row) * 256 + seg * 128);
    const uint4* glo = reinterpret_cast<const uint4*>(
        Wlog + (size_t)(bn + row) * 256 + seg * 128);
    uint4* shi = reinterpret_cast<uint4*>(sm + SM_WHI + row * (WROWB*2) + seg * 256);
    uint4* slo = reinterpret_cast<uint4*>(sm + SM_WLO + row * (WROWB*2) + seg * 256);
    #pragma unroll
    for (int q = 0; q < 16; q++) { shi[q] = ghi[q]; slo[q] = glo[q]; }
    if (tid < 128) {
        int n = bn + tid;
        reinterpret_cast<float*>(sm + SM_BIAS)[tid] = b1[n] + b2[n];
    }
    __syncthreads();
}

// ---------------------------------------------------------------------------
// Shared MMA compute core: fragments + 48 HMMA per k-chunk + epilogue.
// A staged in smem by the caller-provided loader each k-chunk.
// Variadic so brace-level commas in STAGE_A are preserved.
// ---------------------------------------------------------------------------
#define MMA_CORE_BODY(...)                                                      \
    const int tid  = threadIdx.x;                                               \
    const int lane = tid & 31;                                                  \
    const int wid  = tid >> 5;                                                  \
    const int g    = lane >> 2;                                                 \
    const int tig  = lane & 3;                                                  \
    const int m_base = (wid >> 1) * 32;                                         \
    const int n_base = (wid & 1) * 64;                                          \
    const uint32_t* Wwhi = reinterpret_cast<const uint32_t*>(sm + SM_WHI);      \
    const uint32_t* Wwlo = reinterpret_cast<const uint32_t*>(sm + SM_WLO);      \
    const uint32_t* Awhi = reinterpret_cast<const uint32_t*>(sm + SM_AHI);      \
    const uint32_t* Awlo = reinterpret_cast<const uint32_t*>(sm + SM_ALO);      \
    float acc[2][8][4];                                                         \
    _Pragma("unroll")                                                           \
    for (int mf = 0; mf < 2; mf++)                                              \
        _Pragma("unroll")                                                       \
        for (int nf = 0; nf < 8; nf++)                                          \
            _Pragma("unroll")                                                   \
            for (int q = 0; q < 4; q++) acc[mf][nf][q] = 0.f;                   \
    const int arow = tid >> 1;                                                  \
    const int aseg = tid & 1;                                                   \
    for (int kc = 0; kc < 4; kc++) {                                            \
        __syncthreads();                                                        \
        __VA_ARGS__;                                                            \
        __syncthreads();                                                        \
        _Pragma("unroll")                                                       \
        for (int ks = 0; ks < 4; ks++) {                                        \
            const int kwl = ks * 8;                                             \
            const int kwg = kc * 32 + ks * 8;                                   \
            uint32_t ahi[2][4];                                                 \
            uint32_t alo[2][4];                                                 \
            uint32_t bhi[8][2];                                                 \
            uint32_t blo[8][2];                                                 \
            _Pragma("unroll")                                                   \
            for (int mf = 0; mf < 2; mf++) {                                    \
                int r0 = (m_base + mf * 16 + g) * 36 + kwl + tig;               \
                int r1 = r0 + 8 * 36;                                           \
                ahi[mf][0] = Awhi[r0];     ahi[mf][1] = Awhi[r1];               \
                ahi[mf][2] = Awhi[r0 + 4]; ahi[mf][3] = Awhi[r1 + 4];           \
                alo[mf][0] = Awlo[r0];     alo[mf][1] = Awlo[r1];               \
                alo[mf][2] = Awlo[r0 + 4]; alo[mf][3] = Awlo[r1 + 4];           \
            }                                                                   \
            _Pragma("unroll")                                                   \
            for (int nf = 0; nf < 8; nf++) {                                    \
                int rb = (n_base + nf * 8 + g) * 132 + kwg + tig;               \
                bhi[nf][0] = Wwhi[rb]; bhi[nf][1] = Wwhi[rb + 4];               \
                blo[nf][0] = Wwlo[rb]; blo[nf][1] = Wwlo[rb + 4];               \
            }                                                                   \
            _Pragma("unroll")                                                   \
            for (int mf = 0; mf < 2; mf++)                                      \
                _Pragma("unroll")                                               \
                for (int nf = 0; nf < 8; nf++) {                                \
                    MMA_BF16(acc[mf][nf], ahi[mf], bhi[nf]);                    \
                    MMA_BF16(acc[mf][nf], ahi[mf], blo[nf]);                    \
                    MMA_BF16(acc[mf][nf], alo[mf], bhi[nf]);                    \
                }                                                               \
        }                                                                       \
    }                                                                           \
    const float* bias = reinterpret_cast<const float*>(sm + SM_BIAS);           \
    _Pragma("unroll")                                                           \
    for (int mf = 0; mf < 2; mf++) {                                            \
        int row0 = m_base + mf * 16 + g;                                        \
        _Pragma("unroll")                                                       \
        for (int nf = 0; nf < 8; nf++) {                                        \
            int col = n_base + nf * 8 + tig * 2;                                \
            float2 o0 = { acc[mf][nf][0] + bias[col],                           \
                          acc[mf][nf][1] + bias[col + 1] };                     \
            float2 o1 = { acc[mf][nf][2] + bias[col],                           \
                          acc[mf][nf][3] + bias[col + 1] };                     \
            *reinterpret_cast<float2*>(&Crows[(size_t)row0 * 256 + bn + col]) = o0;      \
            *reinterpret_cast<float2*>(&Crows[(size_t)(row0 + 8) * 256 + bn + col]) = o1;\
        }                                                                       \
    }

// A from precomputed bf16 hi/lo (worker path, validated R7)
__device__ __forceinline__ void mma_tile_bf16(
    const __nv_bfloat16* __restrict__ Ahig,
    const __nv_bfloat16* __restrict__ Alog,
    float* __restrict__ Crows, int bn, char* sm)
{
    MMA_CORE_BODY({
        const uint4* ghi = reinterpret_cast<const uint4*>(
            Ahig + (size_t)arow * 256 + kc * 64 + aseg * 32);
        const uint4* glo = reinterpret_cast<const uint4*>(
            Alog + (size_t)arow * 256 + kc * 64 + aseg * 32);
        uint4* shi = reinterpret_cast<uint4*>(sm + SM_AHI + arow * (AROWB*2) + aseg * 64);
        uint4* slo = reinterpret_cast<uint4*>(sm + SM_ALO + arow * (AROWB*2) + aseg * 64);
        _Pragma("unroll")
        for (int q = 0; q < 4; q++) { shi[q] = ghi[q]; slo[q] = glo[q]; }
    });
}

// A from fp32, converted to hi/lo during staging (phase-A path)
__device__ __forceinline__ void mma_tile_f32(
    const float* __restrict__ Arows,
    float* __restrict__ Crows, int bn, char* sm)
{
    MMA_CORE_BODY({
        const float4* gf = reinterpret_cast<const float4*>(
            Arows + (size_t)arow * 256 + kc * 64 + aseg * 32);
        uint32_t hw[16];
        uint32_t lw[16];
        _Pragma("unroll")
        for (int q = 0; q < 8; q++) {
            float4 f = gf[q];
            __nv_bfloat162 h0 = __floats2bfloat162_rn(f.x, f.y);
            __nv_bfloat162 h1 = __floats2bfloat162_rn(f.z, f.w);
            float lx = f.x - __bfloat162float(h0.x);
            float ly = f.y - __bfloat162float(h0.y);
            float lz = f.z - __bfloat162float(h1.x);
            float lw2 = f.w - __bfloat162float(h1.y);
            __nv_bfloat162 l0 = __floats2bfloat162_rn(lx, ly);
            __nv_bfloat162 l1 = __floats2bfloat162_rn(lz, lw2);
            hw[2*q]   = *reinterpret_cast<uint32_t*>(&h0);
            hw[2*q+1] = *reinterpret_cast<uint32_t*>(&h1);
            lw[2*q]   = *reinterpret_cast<uint32_t*>(&l0);
            lw[2*q+1] = *reinterpret_cast<uint32_t*>(&l1);
        }
        uint4* shi = reinterpret_cast<uint4*>(sm + SM_AHI + arow * (AROWB*2) + aseg * 64);
        uint4* slo = reinterpret_cast<uint4*>(sm + SM_ALO + arow * (AROWB*2) + aseg * 64);
        _Pragma("unroll")
        for (int q = 0; q < 4; q++) {
            shi[q] = make_uint4(hw[4*q], hw[4*q+1], hw[4*q+2], hw[4*q+3]);
            slo[q] = make_uint4(lw[4*q], lw[4*q+1], lw[4*q+2], lw[4*q+3]);
        }
    });
}

// ---------------------------------------------------------------------------
// Scan role: thread j owns output j. W row j: 128 floats in regs (64 u64),
// 128 in smem (32 float4, stride 33) — the validated R7 split.
// Double-buffered h, 1 barrier/step. Polls flags every 8 steps (4-chunk LA).
// ---------------------------------------------------------------------------
__device__ __forceinline__ void scan_role(
    const float* __restrict__ xp, const float* __restrict__ Whh,
    int b, float4* Wt,
    __nv_bfloat16* outhi, __nv_bfloat16* outlo, int* prog_out,   // layer1
    float* outf,                                                  // layer2
    const int* poll_flags)
{
    __shared__ __align__(16) float hbuf[2][HID];
    const int j = threadIdx.x;

    unsigned long long w2[64];
    const float4* wrow = reinterpret_cast<const float4*>(Whh + (size_t)j * HID);
    #pragma unroll
    for (int i = 0; i < 32; i++) {
        F4U v; v.v = wrow[i];
        w2[2*i] = v.u[0]; w2[2*i+1] = v.u[1];
    }
    #pragma unroll
    for (int i = 0; i < 32; i++)
        Wt[j * 33 + i] = wrow[32 + i];

    hbuf[0][j] = 0.f;
    __syncthreads();

    const float4* wsrow  = &Wt[j * 33];
    const size_t  stride = (size_t)BATCH * HID;
    const size_t  base   = (size_t)b * HID + j;

    int cur = 0;
    for (int t = 0; t < T_STEPS; t++) {
        if (poll_flags && (t & 7) == 0) {
            int c0 = t >> 1;
            if (j < 8) {
                const int* f = &poll_flags[(c0 + (j >> 1)) * 2 + (j & 1)];
                while (ld_acq(f) == 0) __nanosleep(100);
            }
            __syncthreads();
        }

        float xv = xp[(size_t)t * stride + base];

        const float4* h4 = reinterpret_cast<const float4*>(hbuf[cur]);
        unsigned long long a0 = 0ull, a1 = 0ull, a2 = 0ull, a3 = 0ull;

        #pragma unroll
        for (int i = 0; i < 32; i += 2) {      // k in [0,128): W in regs
            F4U hv0; hv0.v = h4[i];
            a0 = ffma2(w2[2*i],   hv0.u[0], a0);
            a1 = ffma2(w2[2*i+1], hv0.u[1], a1);
            F4U hv1; hv1.v = h4[i+1];
            a2 = ffma2(w2[2*i+2], hv1.u[0], a2);
            a3 = ffma2(w2[2*i+3], hv1.u[1], a3);
        }
        #pragma unroll
        for (int i = 0; i < 32; i += 2) {      // k in [128,256): W in smem
            F4U wv0; wv0.v = wsrow[i];
            F4U hv0; hv0.v = h4[32 + i];
            a0 = ffma2(wv0.u[0], hv0.u[0], a0);
            a1 = ffma2(wv0.u[1], hv0.u[1], a1);
            F4U wv1; wv1.v = wsrow[i+1];
            F4U hv1; hv1.v = h4[33 + i];
            a2 = ffma2(wv1.u[0], hv1.u[0], a2);
            a3 = ffma2(wv1.u[1], hv1.u[1], a3);
        }

        float2 s0 = up2(a0), s1 = up2(a1), s2 = up2(a2), s3 = up2(a3);
        float sum = ((s0.x + s0.y) + (s1.x + s1.y))
                  + ((s2.x + s2.y) + (s3.x + s3.y)) + xv;
        float h = tanhf(sum);

        hbuf[cur ^ 1][j] = h;
        if (outf) {
            outf[(size_t)t * stride + base] = h;
        } else {
            __nv_bfloat16 hv = __float2bfloat16(h);
            outhi[(size_t)t * stride + base] = hv;
            outlo[(size_t)t * stride + base] =
                __float2bfloat16(h - __bfloat162float(hv));
        }
        __syncthreads();
        if (prog_out && j == 0) st_rel(prog_out, t + 1);
        cur ^= 1;
    }
}

// ---------------------------------------------------------------------------
// Pipeline: 148 CTAs, everything after prep.
//   bid 0..63   : layer-1 scan (polls g_xp0flag) -> h1 bf16, publishes prog1
//   bid 64..147 : FIRST phase-A streams (xp0 = x@W_ih0^T+b, sets g_xp0flag)
//     then bid 64..127 : layer-2 scan (polls g_midflag) -> out
//          bid 128..147: HMMA xp1 workers (poll prog1, set g_midflag)
// ---------------------------------------------------------------------------
__global__ __launch_bounds__(256, 1) void pipeline_kernel(
    const float* __restrict__ x,
    const float* __restrict__ W_hh0,
    const float* __restrict__ b_ih0, const float* __restrict__ b_hh0,
    const float* __restrict__ b_ih1, const float* __restrict__ b_hh1,
    const float* __restrict__ W_hh1,
    float* __restrict__ out)
{
    extern __shared__ char sm[];
    const int bid = blockIdx.x;
    const int tid = threadIdx.x;

    if (bid < 64) {
        scan_role(g_buf0, W_hh0, bid, reinterpret_cast<float4*>(sm),
                  g_h1hi, g_h1lo, &g_prog1[bid], nullptr, g_xp0flag);
        return;
    }

    // ---- phase A: xp0 chunks in ascending order ----
    {
        const int s = bid - 64;          // 0..83
        const int half = s & 1;
        const int bn = half * 128;
        const int stream = s >> 1;       // 0..41
        mma_setup_w(sm, g_Whi[0], g_Wlo[0], bn, b_ih0, b_hh0);
        for (int c = stream; c < NCHUNK; c += NPA) {
            mma_tile_f32(x + (size_t)c * 128 * 256,
                         g_buf0 + (size_t)c * 128 * 256, bn, sm);
            __syncthreads();
            if (tid == 0) st_rel(&g_xp0flag[c * 2 + half], 1);
        }
        __syncthreads();
    }

    if (bid < 128) {
        // ---- layer-2 scan ----
        scan_role(g_buf2, W_hh1, bid - 64, reinterpret_cast<float4*>(sm),
                  nullptr, nullptr, nullptr, out, g_midflag);
    } else {
        // ---- xp1 workers ----
        const int w = bid - 128;         // 0..19
        const int half = w & 1;
        const int bn = half * 128;
        const int stream = w >> 1;       // 0..9
        mma_setup_w(sm, g_Whi[1], g_Wlo[1], bn, b_ih1, b_hh1);
        for (int c = stream; c < NCHUNK; c += NWSTR) {
            if (tid < BATCH)
                while (ld_acq(&g_prog1[tid]) < 2 * c + 2) __nanosleep(200);
            __syncthreads();
            mma_tile_bf16(g_h1hi + (size_t)c * 128 * 256,
                          g_h1lo + (size_t)c * 128 * 256,
                          g_buf2 + (size_t)c * 128 * 256, bn, sm);
            __syncthreads();
            if (tid == 0) st_rel(&g_midflag[c * 2 + half], 1);
        }
    }
}

// ---------------------------------------------------------------------------
extern "C" void kernel_launch(void* const* d_in, const int* in_sizes, int n_in,
                              void* d_out, int out_size)
{
    const float* x     = (const float*)d_in[0];
    const float* W_ih0 = (const float*)d_in[1];
    const float* W_hh0 = (const float*)d_in[2];
    const float* b_ih0 = (const float*)d_in[3];
    const float* b_hh0 = (const float*)d_in[4];
    const float* W_ih1 = (const float*)d_in[5];
    const float* W_hh1 = (const float*)d_in[6];
    const float* b_ih1 = (const float*)d_in[7];
    const float* b_hh1 = (const float*)d_in[8];
    float* out = (float*)d_out;

    cudaFuncSetAttribute(pipeline_kernel,
                         cudaFuncAttributeMaxDynamicSharedMemorySize, GEMM_SMEM);

    prep_kernel<<<64, 256>>>(W_ih0, W_ih1);
    pipeline_kernel<<<148, 256, GEMM_SMEM>>>(
        x, W_hh0, b_ih0, b_hh0, b_ih1, b_hh1, W_hh1, out);
}

// round 12
// speedup vs baseline: 1.5705x; 1.1133x over previous
#include <cuda_runtime.h>
#include <cuda_bf16.h>
#include <cstdint>

#define T_STEPS 2048
#define BATCH   64
#define HID     256
#define MROWS   (T_STEPS * BATCH)   // 131072
#define NCHUNK  1024                // 128-row (=2-step) chunks
#define NTILE   (NCHUNK * 2)
#define NPA     42                  // phase-A streams (84 CTAs / 2 halves)
#define NWSTR   10                  // worker streams (20 CTAs / 2 halves)

// GEMM smem layout (bytes) — validated in R7
#define SM_BIAS  0
#define SM_WHI   1024
#define WROWB    264
#define WBYTES   (128 * WROWB * 2)
#define SM_WLO   (SM_WHI + WBYTES)
#define SM_AHI   (SM_WLO + WBYTES)
#define AROWB    72
#define ABYTES   (128 * AROWB * 2)
#define SM_ALO   (SM_AHI + ABYTES)
#define GEMM_SMEM (SM_ALO + ABYTES)  // 173056

// Scan smem: Wt stride 25 float4 (96 floats W + pad): 256*25*16 = 102400 < GEMM_SMEM

__device__ float g_buf0[(size_t)MROWS * HID];   // xp0 fp32
__device__ float g_buf2[(size_t)MROWS * HID];   // xp1 fp32
__device__ __nv_bfloat16 g_h1hi[(size_t)MROWS * HID];
__device__ __nv_bfloat16 g_h1lo[(size_t)MROWS * HID];
__device__ __nv_bfloat16 g_Whi[2][HID * HID];
__device__ __nv_bfloat16 g_Wlo[2][HID * HID];
__device__ int g_prog1[BATCH];
__device__ int g_xp0flag[NTILE];
__device__ int g_midflag[NTILE];

// ---------------------------------------------------------------------------
union F4U { float4 v; unsigned long long u[2]; };
__device__ __forceinline__ unsigned long long ffma2(
    unsigned long long a, unsigned long long b, unsigned long long c)
{
    unsigned long long d;
    asm("fma.rn.f32x2 %0, %1, %2, %3;" : "=l"(d) : "l"(a), "l"(b), "l"(c));
    return d;
}
__device__ __forceinline__ float2 up2(unsigned long long v)
{
    float2 r;
    asm("mov.b64 {%0, %1}, %2;" : "=f"(r.x), "=f"(r.y) : "l"(v));
    return r;
}
__device__ __forceinline__ int ld_acq(const int* p)
{
    int v;
    asm volatile("ld.acquire.gpu.global.b32 %0, [%1];" : "=r"(v) : "l"(p) : "memory");
    return v;
}
__device__ __forceinline__ void st_rel(int* p, int v)
{
    asm volatile("st.release.gpu.global.b32 [%0], %1;" :: "l"(p), "r"(v) : "memory");
}

#define MMA_BF16(d, a, b) \
    asm volatile("mma.sync.aligned.m16n8k16.row.col.f32.bf16.bf16.f32 " \
        "{%0,%1,%2,%3},{%4,%5,%6,%7},{%8,%9},{%0,%1,%2,%3};" \
        : "+f"((d)[0]), "+f"((d)[1]), "+f"((d)[2]), "+f"((d)[3]) \
        : "r"((a)[0]), "r"((a)[1]), "r"((a)[2]), "r"((a)[3]), \
          "r"((b)[0]), "r"((b)[1]))

// ---------------------------------------------------------------------------
// Prep: zero flags, convert W_ih0/W_ih1 to bf16 hi/lo. (~10us)
// ---------------------------------------------------------------------------
__global__ void prep_kernel(const float* __restrict__ Wih0,
                            const float* __restrict__ Wih1)
{
    int idx = blockIdx.x * blockDim.x + threadIdx.x;
    int nthr = gridDim.x * blockDim.x;
    for (int i = idx; i < NTILE; i += nthr) { g_xp0flag[i] = 0; g_midflag[i] = 0; }
    if (idx < BATCH) g_prog1[idx] = 0;
    for (int i = idx; i < 2 * HID * HID; i += nthr) {
        int m = i >> 16, e = i & 0xFFFF;
        float w = (m == 0 ? Wih0 : Wih1)[e];
        __nv_bfloat16 hi = __float2bfloat16(w);
        g_Whi[m][e] = hi;
        g_Wlo[m][e] = __float2bfloat16(w - __bfloat162float(hi));
    }
}

// ---------------------------------------------------------------------------
// Stage W half + bias into smem (validated R7)
// ---------------------------------------------------------------------------
__device__ __forceinline__ void mma_setup_w(
    char* sm, const __nv_bfloat16* Whig, const __nv_bfloat16* Wlog, int bn,
    const float* b1, const float* b2)
{
    const int tid = threadIdx.x;
    const int row = tid >> 1;
    const int seg = tid & 1;
    const uint4* ghi = reinterpret_cast<const uint4*>(
        Whig + (size_t)(bn + row) * 256 + seg * 128);
    const uint4* glo = reinterpret_cast<const uint4*>(
        Wlog + (size_t)(bn + row) * 256 + seg * 128);
    uint4* shi = reinterpret_cast<uint4*>(sm + SM_WHI + row * (WROWB*2) + seg * 256);
    uint4* slo = reinterpret_cast<uint4*>(sm + SM_WLO + row * (WROWB*2) + seg * 256);
    #pragma unroll
    for (int q = 0; q < 16; q++) { shi[q] = ghi[q]; slo[q] = glo[q]; }
    if (tid < 128) {
        int n = bn + tid;
        reinterpret_cast<float*>(sm + SM_BIAS)[tid] = b1[n] + b2[n];
    }
    __syncthreads();
}

// ---------------------------------------------------------------------------
// Shared MMA compute core (validated R7/R10). Variadic: commas OK in STAGE_A.
// ---------------------------------------------------------------------------
#define MMA_CORE_BODY(...)                                                      \
    const int tid  = threadIdx.x;                                               \
    const int lane = tid & 31;                                                  \
    const int wid  = tid >> 5;                                                  \
    const int g    = lane >> 2;                                                 \
    const int tig  = lane & 3;                                                  \
    const int m_base = (wid >> 1) * 32;                                         \
    const int n_base = (wid & 1) * 64;                                          \
    const uint32_t* Wwhi = reinterpret_cast<const uint32_t*>(sm + SM_WHI);      \
    const uint32_t* Wwlo = reinterpret_cast<const uint32_t*>(sm + SM_WLO);      \
    const uint32_t* Awhi = reinterpret_cast<const uint32_t*>(sm + SM_AHI);      \
    const uint32_t* Awlo = reinterpret_cast<const uint32_t*>(sm + SM_ALO);      \
    float acc[2][8][4];                                                         \
    _Pragma("unroll")                                                           \
    for (int mf = 0; mf < 2; mf++)                                              \
        _Pragma("unroll")                                                       \
        for (int nf = 0; nf < 8; nf++)                                          \
            _Pragma("unroll")                                                   \
            for (int q = 0; q < 4; q++) acc[mf][nf][q] = 0.f;                   \
    const int arow = tid >> 1;                                                  \
    const int aseg = tid & 1;                                                   \
    for (int kc = 0; kc < 4; kc++) {                                            \
        __syncthreads();                                                        \
        __VA_ARGS__;                                                            \
        __syncthreads();                                                        \
        _Pragma("unroll")                                                       \
        for (int ks = 0; ks < 4; ks++) {                                        \
            const int kwl = ks * 8;                                             \
            const int kwg = kc * 32 + ks * 8;                                   \
            uint32_t ahi[2][4];                                                 \
            uint32_t alo[2][4];                                                 \
            uint32_t bhi[8][2];                                                 \
            uint32_t blo[8][2];                                                 \
            _Pragma("unroll")                                                   \
            for (int mf = 0; mf < 2; mf++) {                                    \
                int r0 = (m_base + mf * 16 + g) * 36 + kwl + tig;               \
                int r1 = r0 + 8 * 36;                                           \
                ahi[mf][0] = Awhi[r0];     ahi[mf][1] = Awhi[r1];               \
                ahi[mf][2] = Awhi[r0 + 4]; ahi[mf][3] = Awhi[r1 + 4];           \
                alo[mf][0] = Awlo[r0];     alo[mf][1] = Awlo[r1];               \
                alo[mf][2] = Awlo[r0 + 4]; alo[mf][3] = Awlo[r1 + 4];           \
            }                                                                   \
            _Pragma("unroll")                                                   \
            for (int nf = 0; nf < 8; nf++) {                                    \
                int rb = (n_base + nf * 8 + g) * 132 + kwg + tig;               \
                bhi[nf][0] = Wwhi[rb]; bhi[nf][1] = Wwhi[rb + 4];               \
                blo[nf][0] = Wwlo[rb]; blo[nf][1] = Wwlo[rb + 4];               \
            }                                                                   \
            _Pragma("unroll")                                                   \
            for (int mf = 0; mf < 2; mf++)                                      \
                _Pragma("unroll")                                               \
                for (int nf = 0; nf < 8; nf++) {                                \
                    MMA_BF16(acc[mf][nf], ahi[mf], bhi[nf]);                    \
                    MMA_BF16(acc[mf][nf], ahi[mf], blo[nf]);                    \
                    MMA_BF16(acc[mf][nf], alo[mf], bhi[nf]);                    \
                }                                                               \
        }                                                                       \
    }                                                                           \
    const float* bias = reinterpret_cast<const float*>(sm + SM_BIAS);           \
    _Pragma("unroll")                                                           \
    for (int mf = 0; mf < 2; mf++) {                                            \
        int row0 = m_base + mf * 16 + g;                                        \
        _Pragma("unroll")                                                       \
        for (int nf = 0; nf < 8; nf++) {                                        \
            int col = n_base + nf * 8 + tig * 2;                                \
            float2 o0 = { acc[mf][nf][0] + bias[col],                           \
                          acc[mf][nf][1] + bias[col + 1] };                     \
            float2 o1 = { acc[mf][nf][2] + bias[col],                           \
                          acc[mf][nf][3] + bias[col + 1] };                     \
            *reinterpret_cast<float2*>(&Crows[(size_t)row0 * 256 + bn + col]) = o0;      \
            *reinterpret_cast<float2*>(&Crows[(size_t)(row0 + 8) * 256 + bn + col]) = o1;\
        }                                                                       \
    }

// A from precomputed bf16 hi/lo (worker path, validated R7)
__device__ __forceinline__ void mma_tile_bf16(
    const __nv_bfloat16* __restrict__ Ahig,
    const __nv_bfloat16* __restrict__ Alog,
    float* __restrict__ Crows, int bn, char* sm)
{
    MMA_CORE_BODY({
        const uint4* ghi = reinterpret_cast<const uint4*>(
            Ahig + (size_t)arow * 256 + kc * 64 + aseg * 32);
        const uint4* glo = reinterpret_cast<const uint4*>(
            Alog + (size_t)arow * 256 + kc * 64 + aseg * 32);
        uint4* shi = reinterpret_cast<uint4*>(sm + SM_AHI + arow * (AROWB*2) + aseg * 64);
        uint4* slo = reinterpret_cast<uint4*>(sm + SM_ALO + arow * (AROWB*2) + aseg * 64);
        _Pragma("unroll")
        for (int q = 0; q < 4; q++) { shi[q] = ghi[q]; slo[q] = glo[q]; }
    });
}

// A from fp32, converted to hi/lo during staging (phase-A path)
__device__ __forceinline__ void mma_tile_f32(
    const float* __restrict__ Arows,
    float* __restrict__ Crows, int bn, char* sm)
{
    MMA_CORE_BODY({
        const float4* gf = reinterpret_cast<const float4*>(
            Arows + (size_t)arow * 256 + kc * 64 + aseg * 32);
        uint32_t hw[16];
        uint32_t lw[16];
        _Pragma("unroll")
        for (int q = 0; q < 8; q++) {
            float4 f = gf[q];
            __nv_bfloat162 h0 = __floats2bfloat162_rn(f.x, f.y);
            __nv_bfloat162 h1 = __floats2bfloat162_rn(f.z, f.w);
            float lx = f.x - __bfloat162float(h0.x);
            float ly = f.y - __bfloat162float(h0.y);
            float lz = f.z - __bfloat162float(h1.x);
            float lw2 = f.w - __bfloat162float(h1.y);
            __nv_bfloat162 l0 = __floats2bfloat162_rn(lx, ly);
            __nv_bfloat162 l1 = __floats2bfloat162_rn(lz, lw2);
            hw[2*q]   = *reinterpret_cast<uint32_t*>(&h0);
            hw[2*q+1] = *reinterpret_cast<uint32_t*>(&h1);
            lw[2*q]   = *reinterpret_cast<uint32_t*>(&l0);
            lw[2*q+1] = *reinterpret_cast<uint32_t*>(&l1);
        }
        uint4* shi = reinterpret_cast<uint4*>(sm + SM_AHI + arow * (AROWB*2) + aseg * 64);
        uint4* slo = reinterpret_cast<uint4*>(sm + SM_ALO + arow * (AROWB*2) + aseg * 64);
        _Pragma("unroll")
        for (int q = 0; q < 4; q++) {
            shi[q] = make_uint4(hw[4*q], hw[4*q+1], hw[4*q+2], hw[4*q+3]);
            slo[q] = make_uint4(lw[4*q], lw[4*q+1], lw[4*q+2], lw[4*q+3]);
        }
    });
}

// ---------------------------------------------------------------------------
// Scan role: thread j owns output j. W row j: 160 floats in regs (80 u64),
// 96 in smem (24 float4, stride 25 -> conflict-free phases).
// Double-buffered h, 1 barrier/step. Polls flags every 16 steps (8-chunk LA).
// Progress published every 2 steps with a fence.
// ---------------------------------------------------------------------------
__device__ __forceinline__ void scan_role(
    const float* __restrict__ xp, const float* __restrict__ Whh,
    int b, float4* Wt,
    __nv_bfloat16* outhi, __nv_bfloat16* outlo, int* prog_out,   // layer1
    float* outf,                                                  // layer2
    const int* poll_flags)
{
    __shared__ __align__(16) float hbuf[2][HID];
    const int j = threadIdx.x;

    unsigned long long w2[80];
    const float4* wrow = reinterpret_cast<const float4*>(Whh + (size_t)j * HID);
    #pragma unroll
    for (int i = 0; i < 40; i++) {
        F4U v; v.v = wrow[i];
        w2[2*i] = v.u[0]; w2[2*i+1] = v.u[1];
    }
    #pragma unroll
    for (int i = 0; i < 24; i++)
        Wt[j * 25 + i] = wrow[40 + i];

    hbuf[0][j] = 0.f;
    __syncthreads();

    const float4* wsrow  = &Wt[j * 25];
    const size_t  stride = (size_t)BATCH * HID;
    const size_t  base   = (size_t)b * HID + j;

    int cur = 0;
    for (int t = 0; t < T_STEPS; t++) {
        if (poll_flags && (t & 15) == 0) {
            int c0 = t >> 1;
            if (j < 16) {
                const int* f = &poll_flags[(c0 + (j >> 1)) * 2 + (j & 1)];
                while (ld_acq(f) == 0) __nanosleep(100);
            }
            __syncthreads();
        }

        float xv = xp[(size_t)t * stride + base];

        const float4* h4 = reinterpret_cast<const float4*>(hbuf[cur]);
        unsigned long long a0 = 0ull, a1 = 0ull, a2 = 0ull, a3 = 0ull;

        #pragma unroll
        for (int i = 0; i < 40; i += 2) {      // k in [0,160): W in regs
            F4U hv0; hv0.v = h4[i];
            a0 = ffma2(w2[2*i],   hv0.u[0], a0);
            a1 = ffma2(w2[2*i+1], hv0.u[1], a1);
            F4U hv1; hv1.v = h4[i+1];
            a2 = ffma2(w2[2*i+2], hv1.u[0], a2);
            a3 = ffma2(w2[2*i+3], hv1.u[1], a3);
        }
        #pragma unroll
        for (int i = 0; i < 24; i += 2) {      // k in [160,256): W in smem
            F4U wv0; wv0.v = wsrow[i];
            F4U hv0; hv0.v = h4[40 + i];
            a0 = ffma2(wv0.u[0], hv0.u[0], a0);
            a1 = ffma2(wv0.u[1], hv0.u[1], a1);
            F4U wv1; wv1.v = wsrow[i+1];
            F4U hv1; hv1.v = h4[41 + i];
            a2 = ffma2(wv1.u[0], hv1.u[0], a2);
            a3 = ffma2(wv1.u[1], hv1.u[1], a3);
        }

        float2 s0 = up2(a0), s1 = up2(a1), s2 = up2(a2), s3 = up2(a3);
        float sum = ((s0.x + s0.y) + (s1.x + s1.y))
                  + ((s2.x + s2.y) + (s3.x + s3.y)) + xv;
        float h = tanhf(sum);

        hbuf[cur ^ 1][j] = h;
        if (outf) {
            outf[(size_t)t * stride + base] = h;
        } else {
            __nv_bfloat16 hv = __float2bfloat16(h);
            outhi[(size_t)t * stride + base] = hv;
            outlo[(size_t)t * stride + base] =
                __float2bfloat16(h - __bfloat162float(hv));
        }
        __syncthreads();
        if (prog_out && (t & 1) && j == 0) {
            __threadfence();
            st_rel(prog_out, t + 1);
        }
        cur ^= 1;
    }
}

// ---------------------------------------------------------------------------
// Pipeline: 148 CTAs, everything after prep.
//   bid 0..63   : layer-1 scan (polls g_xp0flag) -> h1 bf16, publishes prog1
//   bid 64..147 : FIRST phase-A streams (xp0 = x@W_ih0^T+b, sets g_xp0flag)
//     then bid 64..127 : layer-2 scan (polls g_midflag) -> out
//          bid 128..147: HMMA xp1 workers (poll prog1, set g_midflag)
// ---------------------------------------------------------------------------
__global__ __launch_bounds__(256, 1) void pipeline_kernel(
    const float* __restrict__ x,
    const float* __restrict__ W_hh0,
    const float* __restrict__ b_ih0, const float* __restrict__ b_hh0,
    const float* __restrict__ b_ih1, const float* __restrict__ b_hh1,
    const float* __restrict__ W_hh1,
    float* __restrict__ out)
{
    extern __shared__ char sm[];
    const int bid = blockIdx.x;
    const int tid = threadIdx.x;

    if (bid < 64) {
        scan_role(g_buf0, W_hh0, bid, reinterpret_cast<float4*>(sm),
                  g_h1hi, g_h1lo, &g_prog1[bid], nullptr, g_xp0flag);
        return;
    }

    // ---- phase A: xp0 chunks in ascending order ----
    {
        const int s = bid - 64;          // 0..83
        const int half = s & 1;
        const int bn = half * 128;
        const int stream = s >> 1;       // 0..41
        mma_setup_w(sm, g_Whi[0], g_Wlo[0], bn, b_ih0, b_hh0);
        for (int c = stream; c < NCHUNK; c += NPA) {
            mma_tile_f32(x + (size_t)c * 128 * 256,
                         g_buf0 + (size_t)c * 128 * 256, bn, sm);
            __syncthreads();
            if (tid == 0) st_rel(&g_xp0flag[c * 2 + half], 1);
        }
        __syncthreads();
    }

    if (bid < 128) {
        // ---- layer-2 scan ----
        scan_role(g_buf2, W_hh1, bid - 64, reinterpret_cast<float4*>(sm),
                  nullptr, nullptr, nullptr, out, g_midflag);
    } else {
        // ---- xp1 workers ----
        const int w = bid - 128;         // 0..19
        const int half = w & 1;
        const int bn = half * 128;
        const int stream = w >> 1;       // 0..9
        mma_setup_w(sm, g_Whi[1], g_Wlo[1], bn, b_ih1, b_hh1);
        for (int c = stream; c < NCHUNK; c += NWSTR) {
            if (tid < BATCH)
                while (ld_acq(&g_prog1[tid]) < 2 * c + 2) __nanosleep(200);
            __syncthreads();
            mma_tile_bf16(g_h1hi + (size_t)c * 128 * 256,
                          g_h1lo + (size_t)c * 128 * 256,
                          g_buf2 + (size_t)c * 128 * 256, bn, sm);
            __syncthreads();
            if (tid == 0) st_rel(&g_midflag[c * 2 + half], 1);
        }
    }
}

// ---------------------------------------------------------------------------
extern "C" void kernel_launch(void* const* d_in, const int* in_sizes, int n_in,
                              void* d_out, int out_size)
{
    const float* x     = (const float*)d_in[0];
    const float* W_ih0 = (const float*)d_in[1];
    const float* W_hh0 = (const float*)d_in[2];
    const float* b_ih0 = (const float*)d_in[3];
    const float* b_hh0 = (const float*)d_in[4];
    const float* W_ih1 = (const float*)d_in[5];
    const float* W_hh1 = (const float*)d_in[6];
    const float* b_ih1 = (const float*)d_in[7];
    const float* b_hh1 = (const float*)d_in[8];
    float* out = (float*)d_out;

    cudaFuncSetAttribute(pipeline_kernel,
                         cudaFuncAttributeMaxDynamicSharedMemorySize, GEMM_SMEM);

    prep_kernel<<<64, 256>>>(W_ih0, W_ih1);
    pipeline_kernel<<<148, 256, GEMM_SMEM>>>(
        x, W_hh0, b_ih0, b_hh0, b_ih1, b_hh1, W_hh1, out);
}